// round 10
// baseline (speedup 1.0000x reference)
#include <cuda_runtime.h>
#include <cuda_bf16.h>
#include <cuda_fp16.h>
#include <math.h>
#include <stdint.h>

// ---- fixed problem shape ----
#define NUM_ITEMS 50000
#define NUM_USERS 16384
#define H0 512
#define LAT 256
#define NMAX 262144

// ---- scratch ----
static __device__ __half g_WencT[(size_t)NUM_ITEMS * H0];    // fp16 [items, H0]
static __device__ __half g_wdh[(size_t)NUM_ITEMS * H0];      // fp16 Wdec [items, H0]
static __device__ __half g_x[(size_t)NUM_USERS * H0];        // fp16 encoder input
static __device__ __half g_enc[(size_t)NUM_USERS * LAT];     // fp16 latent
static __device__ __half g_w1[(size_t)LAT * H0];             // fp16 W1
static __device__ __half g_w2[(size_t)H0 * LAT];             // fp16 W2
static __device__ __half g_dec[(size_t)NUM_USERS * H0];      // fp16 decoded
static __device__ int    g_cnt[NUM_USERS];
static __device__ int    g_off[NUM_USERS + 1];
static __device__ int    g_cur[NUM_USERS];
static __device__ int    g_pitem[NMAX];
static __device__ float  g_prate[NMAX];
static __device__ int    g_cnt2[NUM_USERS];                  // target sort
static __device__ int    g_off2[NUM_USERS + 1];
static __device__ int    g_cur2[NUM_USERS];
static __device__ int    g_ptidx[NMAX];
static __device__ int    g_ptitem[NMAX];
static __device__ double g_part[NUM_USERS];
static __device__ int    g_dcount;

// ================= prep (main): transpose W_enc (fp16, 32x64 tiles) + W1/W2->fp16 ======
__global__ void k_prep_main(const float* __restrict__ W, const float* __restrict__ W1,
                            const float* __restrict__ W2) {
    int by = blockIdx.y;
    if (by < 8) {
        // transpose W_enc [H0, NUM_ITEMS] -> g_WencT [NUM_ITEMS, H0] (fp16)
        // tile: 64 h x 32 items; fp16 stores are 128B per item row-chunk
        __shared__ float tile[64][33];
        int t = threadIdx.x;
        int txr = t & 31, tr = t >> 5;                     // read: lane=item, 8 rows/iter
        int col0 = blockIdx.x * 32;                        // item base
        int row0 = by * 64;                                // h base
        #pragma unroll
        for (int j = 0; j < 8; j++) {
            int r = tr + j * 8;                            // 0..63 (h)
            int c = col0 + txr;
            if (c < NUM_ITEMS) tile[r][txr] = W[(size_t)(row0 + r) * NUM_ITEMS + c];
        }
        __syncthreads();
        int txw = t & 31, tw = t >> 5;                     // write: lane=h2, 8 items/iter grp
        #pragma unroll
        for (int j = 0; j < 4; j++) {
            int il = tw + j * 8;                           // 0..31 local item
            int item = col0 + il;
            if (item < NUM_ITEMS) {
                float lo = tile[txw * 2][il];
                float hi = tile[txw * 2 + 1][il];
                ((__half2*)(g_WencT + (size_t)item * H0 + row0))[txw] =
                    __floats2half2_rn(lo, hi);
            }
        }
    } else {
        // W1 / W2 -> fp16
        int i = blockIdx.x * blockDim.x + threadIdx.x;     // float4 units
        const int n1 = LAT * H0 / 4;                       // 32768
        if (i >= 2 * n1) return;
        const float* src; __half* dst; int j;
        if (i < n1) { src = W1; dst = g_w1; j = i; }
        else        { src = W2; dst = g_w2; j = i - n1; }
        float4 v = ((const float4*)src)[j];
        ((__half2*)dst)[j * 2 + 0] = __floats2half2_rn(v.x, v.y);
        ((__half2*)dst)[j * 2 + 1] = __floats2half2_rn(v.z, v.w);
    }
}

// ================= prep (side): Wdec -> fp16 =================
__global__ void k_prep_wdec(const float* __restrict__ Wdec) {
    int idx = blockIdx.x * blockDim.x + threadIdx.x;       // float4 units
    if (idx >= NUM_ITEMS * H0 / 4) return;
    float4 v = ((const float4*)Wdec)[idx];
    ((__half2*)g_wdh)[idx * 2 + 0] = __floats2half2_rn(v.x, v.y);
    ((__half2*)g_wdh)[idx * 2 + 1] = __floats2half2_rn(v.z, v.w);
}

// ================= counting sorts =================
__global__ void k_hist(const int* __restrict__ user, int n) {
    int i = blockIdx.x * blockDim.x + threadIdx.x;
    if (i < n) atomicAdd(&g_cnt[user[i]], 1);
}
__global__ void k_hist2(const int* __restrict__ tuser, int n) {
    int i = blockIdx.x * blockDim.x + threadIdx.x;
    if (i < n) atomicAdd(&g_cnt2[tuser[i]], 1);
}

template <const int* CNT, int* OFF, int* CUR>
__device__ __forceinline__ void scan_impl(int n) {
    int t = threadIdx.x;
    int lane = t & 31, wid = t >> 5;
    int base = t * 16;
    int local[16];
    int s = 0;
    #pragma unroll
    for (int i = 0; i < 16; i++) { local[i] = CNT[base + i]; s += local[i]; }
    int v = s;
    #pragma unroll
    for (int o = 1; o < 32; o <<= 1) {
        int u = __shfl_up_sync(0xffffffffu, v, o);
        if (lane >= o) v += u;
    }
    __shared__ int wsum[32];
    if (lane == 31) wsum[wid] = v;
    __syncthreads();
    if (wid == 0) {
        int w = wsum[lane];
        #pragma unroll
        for (int o = 1; o < 32; o <<= 1) {
            int u = __shfl_up_sync(0xffffffffu, w, o);
            if (lane >= o) w += u;
        }
        wsum[lane] = w;
    }
    __syncthreads();
    int run = (wid ? wsum[wid - 1] : 0) + (v - s);
    #pragma unroll
    for (int i = 0; i < 16; i++) {
        OFF[base + i] = run;
        CUR[base + i] = run;
        run += local[i];
    }
    if (t == 1023) OFF[NUM_USERS] = n;
}

__global__ void k_scanU(int n) { scan_impl<g_cnt, g_off, g_cur>(n); }
__global__ void k_scanT(int n) { scan_impl<g_cnt2, g_off2, g_cur2>(n); }

__global__ void k_scatter(const int* __restrict__ user, const int* __restrict__ item,
                          const float* __restrict__ rating, int n) {
    int i = blockIdx.x * blockDim.x + threadIdx.x;
    if (i < n) {
        int p = atomicAdd(&g_cur[user[i]], 1);
        g_pitem[p] = item[i];
        g_prate[p] = rating[i];
    }
}
__global__ void k_scatter2(const int* __restrict__ tuser, const int* __restrict__ titem,
                           int n) {
    int i = blockIdx.x * blockDim.x + threadIdx.x;
    if (i < n) {
        int p = atomicAdd(&g_cur2[tuser[i]], 1);
        g_ptidx[p] = i;
        g_ptitem[p] = titem[i];
    }
}

// ================= encoder aggregation (fp16 gathers, fp32 accum) -> fp16 x =============
__global__ void k_encode(const float* __restrict__ b_enc) {
    int u = blockIdx.x;
    int t = threadIdx.x;                                   // 128; each handles 4 h
    int s = g_off[u], e = g_off[u + 1];
    const uint2* WT = (const uint2*)g_WencT;
    float4 acc0 = make_float4(0.f, 0.f, 0.f, 0.f);
    float4 acc1 = make_float4(0.f, 0.f, 0.f, 0.f);
    __shared__ int   sit[128];
    __shared__ float srt[128];
    for (int j0 = s; j0 < e; j0 += 128) {
        int c = min(128, e - j0);
        if (t < c) { sit[t] = g_pitem[j0 + t]; srt[t] = g_prate[j0 + t]; }
        __syncthreads();
        int q = 0;
        for (; q + 1 < c; q += 2) {
            int i0 = sit[q], i1 = sit[q + 1];
            float r0 = srt[q], r1 = srt[q + 1];
            uint2 w0 = WT[(size_t)i0 * 128 + t];
            uint2 w1 = WT[(size_t)i1 * 128 + t];
            float2 a = __half22float2(*(__half2*)&w0.x);
            float2 b = __half22float2(*(__half2*)&w0.y);
            float2 cc = __half22float2(*(__half2*)&w1.x);
            float2 d = __half22float2(*(__half2*)&w1.y);
            acc0.x = fmaf(r0, a.x, acc0.x); acc1.x = fmaf(r1, cc.x, acc1.x);
            acc0.y = fmaf(r0, a.y, acc0.y); acc1.y = fmaf(r1, cc.y, acc1.y);
            acc0.z = fmaf(r0, b.x, acc0.z); acc1.z = fmaf(r1, d.x, acc1.z);
            acc0.w = fmaf(r0, b.y, acc0.w); acc1.w = fmaf(r1, d.y, acc1.w);
        }
        if (q < c) {
            int i0 = sit[q]; float r0 = srt[q];
            uint2 w0 = WT[(size_t)i0 * 128 + t];
            float2 a = __half22float2(*(__half2*)&w0.x);
            float2 b = __half22float2(*(__half2*)&w0.y);
            acc0.x = fmaf(r0, a.x, acc0.x);
            acc0.y = fmaf(r0, a.y, acc0.y);
            acc0.z = fmaf(r0, b.x, acc0.z);
            acc0.w = fmaf(r0, b.y, acc0.w);
        }
        __syncthreads();
    }
    float4 b = ((const float4*)b_enc)[t];
    float vx = tanhf(acc0.x + acc1.x + b.x);
    float vy = tanhf(acc0.y + acc1.y + b.y);
    float vz = tanhf(acc0.z + acc1.z + b.z);
    float vw = tanhf(acc0.w + acc1.w + b.w);
    size_t o2 = (size_t)u * 256 + t * 2;
    ((__half2*)g_x)[o2 + 0] = __floats2half2_rn(vx, vy);
    ((__half2*)g_x)[o2 + 1] = __floats2half2_rn(vz, vw);
}

// ================= fp16 single-pass tensor-core GEMM =================
#define MMA_F16(c, a0, a1, a2, a3, b0, b1)                                          \
    asm volatile("mma.sync.aligned.m16n8k16.row.col.f32.f16.f16.f32 "               \
                 "{%0,%1,%2,%3},{%4,%5,%6,%7},{%8,%9},{%0,%1,%2,%3};"               \
                 : "+f"(c[0]), "+f"(c[1]), "+f"(c[2]), "+f"(c[3])                   \
                 : "r"(a0), "r"(a1), "r"(a2), "r"(a3), "r"(b0), "r"(b1))

#define SPITCH 136
#define ARRU32 (16 * SPITCH)
#define BUFU32 (2 * ARRU32)
#define GEMM_SMEM ((2 * BUFU32 + 128) * 4)

__global__ void __launch_bounds__(256, 2)
k_gemm(const __half* __restrict__ A, const __half* __restrict__ B,
       const float* __restrict__ bias, __half* __restrict__ C,
       int M, int N, int K) {
    extern __shared__ uint32_t sm[];
    float* bias_s = (float*)(sm + 2 * BUFU32);

    int tid = threadIdx.x;
    int lane = tid & 31;
    int wid = tid >> 5;
    int warp_m = wid & 1;
    int warp_n = wid >> 1;
    int gr = lane >> 2;
    int gc = lane & 3;

    int bm = blockIdx.y * 128;
    int bn = blockIdx.x * 128;

    if (tid < 128) bias_s[tid] = bias[bn + tid];

    float acc[4][4][4];
    #pragma unroll
    for (int i = 0; i < 4; i++)
        #pragma unroll
        for (int j = 0; j < 4; j++)
            #pragma unroll
            for (int q = 0; q < 4; q++) acc[i][j][q] = 0.f;

    const int mb = warp_m * 64;
    const int nb = warp_n * 32;
    const int r    = tid >> 1;
    const int half = tid & 1;
    const int kb2  = half * 8;

    const __half* pA = A + (size_t)(bm + r) * K + half * 16;
    const __half* pB = B + (size_t)(bn + r) * K + half * 16;

    uint4 rA0, rA1, rB0, rB1;

#define LDG_CHUNK(k0)                                                   \
    do {                                                                \
        rA0 = *(const uint4*)(pA + (k0));                               \
        rA1 = *(const uint4*)(pA + (k0) + 8);                           \
        rB0 = *(const uint4*)(pB + (k0));                               \
        rB1 = *(const uint4*)(pB + (k0) + 8);                           \
    } while (0)

#define STS_CHUNK(buf)                                                  \
    do {                                                                \
        uint32_t* bA = sm + (buf) * BUFU32;                             \
        uint32_t* bB = bA + ARRU32;                                     \
        bA[(kb2 + 0) * SPITCH + r] = rA0.x;                             \
        bA[(kb2 + 1) * SPITCH + r] = rA0.y;                             \
        bA[(kb2 + 2) * SPITCH + r] = rA0.z;                             \
        bA[(kb2 + 3) * SPITCH + r] = rA0.w;                             \
        bA[(kb2 + 4) * SPITCH + r] = rA1.x;                             \
        bA[(kb2 + 5) * SPITCH + r] = rA1.y;                             \
        bA[(kb2 + 6) * SPITCH + r] = rA1.z;                             \
        bA[(kb2 + 7) * SPITCH + r] = rA1.w;                             \
        bB[(kb2 + 0) * SPITCH + r] = rB0.x;                             \
        bB[(kb2 + 1) * SPITCH + r] = rB0.y;                             \
        bB[(kb2 + 2) * SPITCH + r] = rB0.z;                             \
        bB[(kb2 + 3) * SPITCH + r] = rB0.w;                             \
        bB[(kb2 + 4) * SPITCH + r] = rB1.x;                             \
        bB[(kb2 + 5) * SPITCH + r] = rB1.y;                             \
        bB[(kb2 + 6) * SPITCH + r] = rB1.z;                             \
        bB[(kb2 + 7) * SPITCH + r] = rB1.w;                             \
    } while (0)

    const int NC = K / 32;
    LDG_CHUNK(0);
    STS_CHUNK(0);
    __syncthreads();

    for (int c = 0; c < NC; c++) {
        if (c + 1 < NC) LDG_CHUNK((c + 1) * 32);

        const uint32_t* bA = sm + (c & 1) * BUFU32;
        const uint32_t* bB = bA + ARRU32;

        #pragma unroll
        for (int ks = 0; ks < 2; ks++) {
            int kb = ks * 8;
            uint32_t Bf[4][2];
            #pragma unroll
            for (int nt = 0; nt < 4; nt++) {
                int n0 = nb + nt * 8 + gr;
                Bf[nt][0] = bB[(kb + gc) * SPITCH + n0];
                Bf[nt][1] = bB[(kb + gc + 4) * SPITCH + n0];
            }
            #pragma unroll
            for (int mt = 0; mt < 4; mt++) {
                int m0 = mb + mt * 16 + gr;
                uint32_t Af[4];
                Af[0] = bA[(kb + gc) * SPITCH + m0];
                Af[1] = bA[(kb + gc) * SPITCH + m0 + 8];
                Af[2] = bA[(kb + gc + 4) * SPITCH + m0];
                Af[3] = bA[(kb + gc + 4) * SPITCH + m0 + 8];
                #pragma unroll
                for (int nt = 0; nt < 4; nt++)
                    MMA_F16(acc[mt][nt], Af[0], Af[1], Af[2], Af[3],
                            Bf[nt][0], Bf[nt][1]);
            }
        }
        if (c + 1 < NC) STS_CHUNK((c + 1) & 1);
        __syncthreads();
    }

    #pragma unroll
    for (int nt = 0; nt < 4; nt++) {
        int nc = nb + nt * 8 + gc * 2;
        float2 bv = make_float2(bias_s[nc], bias_s[nc + 1]);
        int n0 = bn + nc;
        #pragma unroll
        for (int mt = 0; mt < 4; mt++) {
            int m0 = bm + mb + mt * 16 + gr;
            float v00 = tanhf(acc[mt][nt][0] + bv.x);
            float v01 = tanhf(acc[mt][nt][1] + bv.y);
            float v10 = tanhf(acc[mt][nt][2] + bv.x);
            float v11 = tanhf(acc[mt][nt][3] + bv.y);
            *(__half2*)&C[(size_t)m0 * N + n0] = __floats2half2_rn(v00, v01);
            *(__half2*)&C[(size_t)(m0 + 8) * N + n0] = __floats2half2_rn(v10, v11);
        }
    }
}

// ================= decoder v2: block per user, dec row in smem =================
__device__ __forceinline__ float dot_u4(uint4 a, uint4 b) {
    float s = 0.f;
    float2 f, g;
    f = __half22float2(*(__half2*)&a.x); g = __half22float2(*(__half2*)&b.x);
    s = fmaf(f.x, g.x, s); s = fmaf(f.y, g.y, s);
    f = __half22float2(*(__half2*)&a.y); g = __half22float2(*(__half2*)&b.y);
    s = fmaf(f.x, g.x, s); s = fmaf(f.y, g.y, s);
    f = __half22float2(*(__half2*)&a.z); g = __half22float2(*(__half2*)&b.z);
    s = fmaf(f.x, g.x, s); s = fmaf(f.y, g.y, s);
    f = __half22float2(*(__half2*)&a.w); g = __half22float2(*(__half2*)&b.w);
    s = fmaf(f.x, g.x, s); s = fmaf(f.y, g.y, s);
    return s;
}

__global__ void k_decode2(const float* __restrict__ trating,
                          const float* __restrict__ bdec, float* __restrict__ out,
                          int nt, int write_loss) {
    int u = blockIdx.x;                                    // one block per user
    int t = threadIdx.x;                                   // 128 threads, 4 warps
    int warp = t >> 5, lane = t & 31;
    int s = g_off2[u], e = g_off2[u + 1];
    __shared__ uint4 sdec[64];                             // 1 KB decoded row
    if (e > s) {
        if (t < 64) sdec[t] = ((const uint4*)(g_dec + (size_t)u * 512))[t];
    }
    __syncthreads();
    double mine = 0.0;
    for (int idx = s + warp; idx < e; idx += 4) {
        int it   = g_ptitem[idx];
        int tidx = g_ptidx[idx];
        const uint4* w = (const uint4*)(g_wdh + (size_t)it * 512);
        uint4 b0 = w[lane], b1 = w[32 + lane];
        float acc = dot_u4(sdec[lane], b0) + dot_u4(sdec[32 + lane], b1);
        #pragma unroll
        for (int o = 16; o; o >>= 1) acc += __shfl_xor_sync(0xffffffffu, acc, o);
        if (lane == 0) {
            float pred = acc + bdec[it];
            out[tidx] = pred;
            float d = pred - trating[tidx];
            mine += (double)d * (double)d;
        }
    }
    __shared__ double part_s[4];
    __shared__ int is_last;
    if (lane == 0) part_s[warp] = mine;
    __syncthreads();
    if (t == 0) {
        double ss = part_s[0] + part_s[1] + part_s[2] + part_s[3];
        g_part[u] = ss;
        __threadfence();
        int done = atomicAdd(&g_dcount, 1);
        is_last = (done == (int)gridDim.x - 1);
        if (is_last) g_dcount = 0;                         // self-reset for replay
    }
    __syncthreads();
    if (is_last) {
        int nb = (int)gridDim.x;
        double s2 = 0.0;
        for (int i = t; i < nb; i += 128) s2 += g_part[i];
        __shared__ double red[4];
        #pragma unroll
        for (int o = 16; o; o >>= 1) s2 += __shfl_xor_sync(0xffffffffu, s2, o);
        if (lane == 0) red[warp] = s2;
        __syncthreads();
        if (t == 0) {
            double tot = red[0] + red[1] + red[2] + red[3];
            if (write_loss) out[nt] = (float)(tot / (double)nt);
        }
    }
}

// ================= launch (3 forked branches) =================
extern "C" void kernel_launch(void* const* d_in, const int* in_sizes, int n_in,
                              void* d_out, int out_size) {
    const int*   user    = (const int*)d_in[0];
    const int*   item    = (const int*)d_in[1];
    const float* rating  = (const float*)d_in[2];
    const int*   tuser   = (const int*)d_in[3];
    const int*   titem   = (const int*)d_in[4];
    const float* trating = (const float*)d_in[5];
    const float* W_enc   = (const float*)d_in[6];
    const float* b_enc   = (const float*)d_in[7];
    const float* W1      = (const float*)d_in[8];
    const float* b1      = (const float*)d_in[9];
    const float* W2      = (const float*)d_in[10];
    const float* b2      = (const float*)d_in[11];
    const float* W_dec   = (const float*)d_in[12];
    const float* b_dec   = (const float*)d_in[13];
    float* out = (float*)d_out;

    int N  = in_sizes[0];
    int NT = in_sizes[3];
    (void)n_in;

    void *cnt_ptr, *cnt2_ptr, *x_p, *enc_p, *w1_p, *w2_p, *dec_p;
    cudaGetSymbolAddress(&cnt_ptr, g_cnt);
    cudaGetSymbolAddress(&cnt2_ptr, g_cnt2);
    cudaGetSymbolAddress(&x_p, g_x);
    cudaGetSymbolAddress(&enc_p, g_enc);
    cudaGetSymbolAddress(&w1_p, g_w1);
    cudaGetSymbolAddress(&w2_p, g_w2);
    cudaGetSymbolAddress(&dec_p, g_dec);

    cudaFuncSetAttribute(k_gemm, cudaFuncAttributeMaxDynamicSharedMemorySize, GEMM_SMEM);

    // side streams + events, created once on the (uncaptured) correctness call
    static cudaStream_t s1 = nullptr, s2 = nullptr, s3 = nullptr;
    static cudaEvent_t evA = nullptr, evB = nullptr, ev1 = nullptr, ev2 = nullptr,
                       ev3 = nullptr;
    if (!s1) {
        cudaStreamCreateWithFlags(&s1, cudaStreamNonBlocking);
        cudaStreamCreateWithFlags(&s2, cudaStreamNonBlocking);
        cudaStreamCreateWithFlags(&s3, cudaStreamNonBlocking);
        cudaEventCreateWithFlags(&evA, cudaEventDisableTiming);
        cudaEventCreateWithFlags(&evB, cudaEventDisableTiming);
        cudaEventCreateWithFlags(&ev1, cudaEventDisableTiming);
        cudaEventCreateWithFlags(&ev2, cudaEventDisableTiming);
        cudaEventCreateWithFlags(&ev3, cudaEventDisableTiming);
    }

    // main: zero user counters, then fork
    cudaMemsetAsync(cnt_ptr, 0, NUM_USERS * sizeof(int), 0);
    cudaEventRecord(evA, 0);

    // ---- branch S (s1): user counting sort ----
    cudaStreamWaitEvent(s1, evA, 0);
    k_hist<<<(N + 255) / 256, 256, 0, s1>>>(user, N);
    k_scanU<<<1, 1024, 0, s1>>>(N);
    k_scatter<<<(N + 255) / 256, 256, 0, s1>>>(user, item, rating, N);
    cudaEventRecord(ev1, s1);

    // ---- branch T (s3): target counting sort ----
    cudaStreamWaitEvent(s3, evA, 0);
    cudaMemsetAsync(cnt2_ptr, 0, NUM_USERS * sizeof(int), s3);
    k_hist2<<<(NT + 255) / 256, 256, 0, s3>>>(tuser, NT);
    k_scanT<<<1, 1024, 0, s3>>>(NT);
    k_scatter2<<<(NT + 255) / 256, 256, 0, s3>>>(tuser, titem, NT);
    cudaEventRecord(ev3, s3);

    // ---- main: transpose W_enc + W1/W2 (parallel with sorts) ----
    {
        dim3 g((NUM_ITEMS + 31) / 32, 9);
        k_prep_main<<<g, 256>>>(W_enc, W1, W2);
    }
    cudaEventRecord(evB, 0);

    // ---- branch D (s2): Wdec -> fp16 (parallel with encode + GEMMs) ----
    cudaStreamWaitEvent(s2, evB, 0);
    k_prep_wdec<<<(NUM_ITEMS * H0 / 4 + 255) / 256, 256, 0, s2>>>(W_dec);
    cudaEventRecord(ev2, s2);

    // ---- main: join user sort, then encode + GEMMs ----
    cudaStreamWaitEvent(0, ev1, 0);
    k_encode<<<NUM_USERS, 128>>>(b_enc);
    {
        dim3 g1(LAT / 128, NUM_USERS / 128);
        k_gemm<<<g1, 256, GEMM_SMEM>>>((const __half*)x_p, (const __half*)w1_p,
                                       b1, (__half*)enc_p, NUM_USERS, LAT, H0);
        dim3 g2(H0 / 128, NUM_USERS / 128);
        k_gemm<<<g2, 256, GEMM_SMEM>>>((const __half*)enc_p, (const __half*)w2_p,
                                       b2, (__half*)dec_p, NUM_USERS, H0, LAT);
    }

    // ---- main: join Wdec + target sort, then decode + loss ----
    cudaStreamWaitEvent(0, ev2, 0);
    cudaStreamWaitEvent(0, ev3, 0);
    k_decode2<<<NUM_USERS, 128>>>(trating, b_dec, out, NT, out_size > NT ? 1 : 0);
}

// round 11
// speedup vs baseline: 1.0507x; 1.0507x over previous
#include <cuda_runtime.h>
#include <cuda_bf16.h>
#include <cuda_fp16.h>
#include <math.h>
#include <stdint.h>

// ---- fixed problem shape ----
#define NUM_ITEMS 50000
#define NUM_USERS 16384
#define H0 512
#define LAT 256
#define NMAX 262144

// ---- scratch ----
static __device__ __half g_WencT[(size_t)NUM_ITEMS * H0];    // fp16 [items, H0]
static __device__ __half g_wdh[(size_t)NUM_ITEMS * H0];      // fp16 Wdec [items, H0]
static __device__ __half g_x[(size_t)NUM_USERS * H0];        // fp16 encoder input
static __device__ __half g_enc[(size_t)NUM_USERS * LAT];     // fp16 latent
static __device__ __half g_w1[(size_t)LAT * H0];             // fp16 W1
static __device__ __half g_w2[(size_t)H0 * LAT];             // fp16 W2
static __device__ __half g_dec[(size_t)NUM_USERS * H0];      // fp16 decoded
static __device__ int    g_cnt[NUM_USERS];
static __device__ int    g_off[NUM_USERS + 1];
static __device__ int    g_cur[NUM_USERS];
static __device__ int    g_pitem[NMAX];
static __device__ float  g_prate[NMAX];
static __device__ double g_part[NMAX / 32];
static __device__ int    g_dcount;

// ================= prep (main): transpose W_enc (fp16, 64h x 32item tiles) + W1/W2 ======
__global__ void k_prep_main(const float* __restrict__ W, const float* __restrict__ W1,
                            const float* __restrict__ W2) {
    int by = blockIdx.y;
    if (by < 8) {
        // transpose W_enc [H0, NUM_ITEMS] -> g_WencT [NUM_ITEMS, H0] (fp16)
        // fp16 stores are full 128B per item row-chunk
        __shared__ float tile[64][33];
        int t = threadIdx.x;
        int txr = t & 31, tr = t >> 5;
        int col0 = blockIdx.x * 32;                        // item base
        int row0 = by * 64;                                // h base
        #pragma unroll
        for (int j = 0; j < 8; j++) {
            int r = tr + j * 8;
            int c = col0 + txr;
            if (c < NUM_ITEMS) tile[r][txr] = W[(size_t)(row0 + r) * NUM_ITEMS + c];
        }
        __syncthreads();
        int txw = t & 31, tw = t >> 5;
        #pragma unroll
        for (int j = 0; j < 4; j++) {
            int il = tw + j * 8;
            int item = col0 + il;
            if (item < NUM_ITEMS) {
                float lo = tile[txw * 2][il];
                float hi = tile[txw * 2 + 1][il];
                ((__half2*)(g_WencT + (size_t)item * H0 + row0))[txw] =
                    __floats2half2_rn(lo, hi);
            }
        }
    } else {
        // W1 / W2 -> fp16
        int i = blockIdx.x * blockDim.x + threadIdx.x;     // float4 units
        const int n1 = LAT * H0 / 4;                       // 32768
        if (i >= 2 * n1) return;
        const float* src; __half* dst; int j;
        if (i < n1) { src = W1; dst = g_w1; j = i; }
        else        { src = W2; dst = g_w2; j = i - n1; }
        float4 v = ((const float4*)src)[j];
        ((__half2*)dst)[j * 2 + 0] = __floats2half2_rn(v.x, v.y);
        ((__half2*)dst)[j * 2 + 1] = __floats2half2_rn(v.z, v.w);
    }
}

// ================= prep (side): Wdec -> fp16 =================
__global__ void k_prep_wdec(const float* __restrict__ Wdec) {
    int idx = blockIdx.x * blockDim.x + threadIdx.x;       // float4 units
    if (idx >= NUM_ITEMS * H0 / 4) return;
    float4 v = ((const float4*)Wdec)[idx];
    ((__half2*)g_wdh)[idx * 2 + 0] = __floats2half2_rn(v.x, v.y);
    ((__half2*)g_wdh)[idx * 2 + 1] = __floats2half2_rn(v.z, v.w);
}

// ================= counting sort =================
__global__ void k_hist(const int* __restrict__ user, int n) {
    int i = blockIdx.x * blockDim.x + threadIdx.x;
    if (i < n) atomicAdd(&g_cnt[user[i]], 1);
}

__global__ void k_scan(int n) {
    int t = threadIdx.x;
    int lane = t & 31, wid = t >> 5;
    int base = t * 16;
    int local[16];
    int s = 0;
    #pragma unroll
    for (int i = 0; i < 16; i++) { local[i] = g_cnt[base + i]; s += local[i]; }
    int v = s;
    #pragma unroll
    for (int o = 1; o < 32; o <<= 1) {
        int u = __shfl_up_sync(0xffffffffu, v, o);
        if (lane >= o) v += u;
    }
    __shared__ int wsum[32];
    if (lane == 31) wsum[wid] = v;
    __syncthreads();
    if (wid == 0) {
        int w = wsum[lane];
        #pragma unroll
        for (int o = 1; o < 32; o <<= 1) {
            int u = __shfl_up_sync(0xffffffffu, w, o);
            if (lane >= o) w += u;
        }
        wsum[lane] = w;
    }
    __syncthreads();
    int run = (wid ? wsum[wid - 1] : 0) + (v - s);
    #pragma unroll
    for (int i = 0; i < 16; i++) {
        g_off[base + i] = run;
        g_cur[base + i] = run;
        run += local[i];
    }
    if (t == 1023) g_off[NUM_USERS] = n;
}

__global__ void k_scatter(const int* __restrict__ user, const int* __restrict__ item,
                          const float* __restrict__ rating, int n) {
    int i = blockIdx.x * blockDim.x + threadIdx.x;
    if (i < n) {
        int p = atomicAdd(&g_cur[user[i]], 1);
        g_pitem[p] = item[i];
        g_prate[p] = rating[i];
    }
}

// ================= encoder aggregation (fp16 gathers, fp32 accum) -> fp16 x =============
__global__ void k_encode(const float* __restrict__ b_enc) {
    int u = blockIdx.x;
    int t = threadIdx.x;                                   // 128; each handles 4 h
    int s = g_off[u], e = g_off[u + 1];
    const uint2* WT = (const uint2*)g_WencT;
    float4 acc0 = make_float4(0.f, 0.f, 0.f, 0.f);
    float4 acc1 = make_float4(0.f, 0.f, 0.f, 0.f);
    __shared__ int   sit[128];
    __shared__ float srt[128];
    for (int j0 = s; j0 < e; j0 += 128) {
        int c = min(128, e - j0);
        if (t < c) { sit[t] = g_pitem[j0 + t]; srt[t] = g_prate[j0 + t]; }
        __syncthreads();
        int q = 0;
        for (; q + 1 < c; q += 2) {
            int i0 = sit[q], i1 = sit[q + 1];
            float r0 = srt[q], r1 = srt[q + 1];
            uint2 w0 = WT[(size_t)i0 * 128 + t];
            uint2 w1 = WT[(size_t)i1 * 128 + t];
            float2 a = __half22float2(*(__half2*)&w0.x);
            float2 b = __half22float2(*(__half2*)&w0.y);
            float2 cc = __half22float2(*(__half2*)&w1.x);
            float2 d = __half22float2(*(__half2*)&w1.y);
            acc0.x = fmaf(r0, a.x, acc0.x); acc1.x = fmaf(r1, cc.x, acc1.x);
            acc0.y = fmaf(r0, a.y, acc0.y); acc1.y = fmaf(r1, cc.y, acc1.y);
            acc0.z = fmaf(r0, b.x, acc0.z); acc1.z = fmaf(r1, d.x, acc1.z);
            acc0.w = fmaf(r0, b.y, acc0.w); acc1.w = fmaf(r1, d.y, acc1.w);
        }
        if (q < c) {
            int i0 = sit[q]; float r0 = srt[q];
            uint2 w0 = WT[(size_t)i0 * 128 + t];
            float2 a = __half22float2(*(__half2*)&w0.x);
            float2 b = __half22float2(*(__half2*)&w0.y);
            acc0.x = fmaf(r0, a.x, acc0.x);
            acc0.y = fmaf(r0, a.y, acc0.y);
            acc0.z = fmaf(r0, b.x, acc0.z);
            acc0.w = fmaf(r0, b.y, acc0.w);
        }
        __syncthreads();
    }
    float4 b = ((const float4*)b_enc)[t];
    float vx = tanhf(acc0.x + acc1.x + b.x);
    float vy = tanhf(acc0.y + acc1.y + b.y);
    float vz = tanhf(acc0.z + acc1.z + b.z);
    float vw = tanhf(acc0.w + acc1.w + b.w);
    size_t o2 = (size_t)u * 256 + t * 2;
    ((__half2*)g_x)[o2 + 0] = __floats2half2_rn(vx, vy);
    ((__half2*)g_x)[o2 + 1] = __floats2half2_rn(vz, vw);
}

// ================= fp16 single-pass tensor-core GEMM =================
#define MMA_F16(c, a0, a1, a2, a3, b0, b1)                                          \
    asm volatile("mma.sync.aligned.m16n8k16.row.col.f32.f16.f16.f32 "               \
                 "{%0,%1,%2,%3},{%4,%5,%6,%7},{%8,%9},{%0,%1,%2,%3};"               \
                 : "+f"(c[0]), "+f"(c[1]), "+f"(c[2]), "+f"(c[3])                   \
                 : "r"(a0), "r"(a1), "r"(a2), "r"(a3), "r"(b0), "r"(b1))

#define SPITCH 136
#define ARRU32 (16 * SPITCH)
#define BUFU32 (2 * ARRU32)
#define GEMM_SMEM ((2 * BUFU32 + 128) * 4)

__global__ void __launch_bounds__(256, 2)
k_gemm(const __half* __restrict__ A, const __half* __restrict__ B,
       const float* __restrict__ bias, __half* __restrict__ C,
       int M, int N, int K) {
    extern __shared__ uint32_t sm[];
    float* bias_s = (float*)(sm + 2 * BUFU32);

    int tid = threadIdx.x;
    int lane = tid & 31;
    int wid = tid >> 5;
    int warp_m = wid & 1;
    int warp_n = wid >> 1;
    int gr = lane >> 2;
    int gc = lane & 3;

    int bm = blockIdx.y * 128;
    int bn = blockIdx.x * 128;

    if (tid < 128) bias_s[tid] = bias[bn + tid];

    float acc[4][4][4];
    #pragma unroll
    for (int i = 0; i < 4; i++)
        #pragma unroll
        for (int j = 0; j < 4; j++)
            #pragma unroll
            for (int q = 0; q < 4; q++) acc[i][j][q] = 0.f;

    const int mb = warp_m * 64;
    const int nb = warp_n * 32;
    const int r    = tid >> 1;
    const int half = tid & 1;
    const int kb2  = half * 8;

    const __half* pA = A + (size_t)(bm + r) * K + half * 16;
    const __half* pB = B + (size_t)(bn + r) * K + half * 16;

    uint4 rA0, rA1, rB0, rB1;

#define LDG_CHUNK(k0)                                                   \
    do {                                                                \
        rA0 = *(const uint4*)(pA + (k0));                               \
        rA1 = *(const uint4*)(pA + (k0) + 8);                           \
        rB0 = *(const uint4*)(pB + (k0));                               \
        rB1 = *(const uint4*)(pB + (k0) + 8);                           \
    } while (0)

#define STS_CHUNK(buf)                                                  \
    do {                                                                \
        uint32_t* bA = sm + (buf) * BUFU32;                             \
        uint32_t* bB = bA + ARRU32;                                     \
        bA[(kb2 + 0) * SPITCH + r] = rA0.x;                             \
        bA[(kb2 + 1) * SPITCH + r] = rA0.y;                             \
        bA[(kb2 + 2) * SPITCH + r] = rA0.z;                             \
        bA[(kb2 + 3) * SPITCH + r] = rA0.w;                             \
        bA[(kb2 + 4) * SPITCH + r] = rA1.x;                             \
        bA[(kb2 + 5) * SPITCH + r] = rA1.y;                             \
        bA[(kb2 + 6) * SPITCH + r] = rA1.z;                             \
        bA[(kb2 + 7) * SPITCH + r] = rA1.w;                             \
        bB[(kb2 + 0) * SPITCH + r] = rB0.x;                             \
        bB[(kb2 + 1) * SPITCH + r] = rB0.y;                             \
        bB[(kb2 + 2) * SPITCH + r] = rB0.z;                             \
        bB[(kb2 + 3) * SPITCH + r] = rB0.w;                             \
        bB[(kb2 + 4) * SPITCH + r] = rB1.x;                             \
        bB[(kb2 + 5) * SPITCH + r] = rB1.y;                             \
        bB[(kb2 + 6) * SPITCH + r] = rB1.z;                             \
        bB[(kb2 + 7) * SPITCH + r] = rB1.w;                             \
    } while (0)

    const int NC = K / 32;
    LDG_CHUNK(0);
    STS_CHUNK(0);
    __syncthreads();

    for (int c = 0; c < NC; c++) {
        if (c + 1 < NC) LDG_CHUNK((c + 1) * 32);

        const uint32_t* bA = sm + (c & 1) * BUFU32;
        const uint32_t* bB = bA + ARRU32;

        #pragma unroll
        for (int ks = 0; ks < 2; ks++) {
            int kb = ks * 8;
            uint32_t Bf[4][2];
            #pragma unroll
            for (int nt = 0; nt < 4; nt++) {
                int n0 = nb + nt * 8 + gr;
                Bf[nt][0] = bB[(kb + gc) * SPITCH + n0];
                Bf[nt][1] = bB[(kb + gc + 4) * SPITCH + n0];
            }
            #pragma unroll
            for (int mt = 0; mt < 4; mt++) {
                int m0 = mb + mt * 16 + gr;
                uint32_t Af[4];
                Af[0] = bA[(kb + gc) * SPITCH + m0];
                Af[1] = bA[(kb + gc) * SPITCH + m0 + 8];
                Af[2] = bA[(kb + gc + 4) * SPITCH + m0];
                Af[3] = bA[(kb + gc + 4) * SPITCH + m0 + 8];
                #pragma unroll
                for (int nt = 0; nt < 4; nt++)
                    MMA_F16(acc[mt][nt], Af[0], Af[1], Af[2], Af[3],
                            Bf[nt][0], Bf[nt][1]);
            }
        }
        if (c + 1 < NC) STS_CHUNK((c + 1) & 1);
        __syncthreads();
    }

    #pragma unroll
    for (int nt = 0; nt < 4; nt++) {
        int nc = nb + nt * 8 + gc * 2;
        float2 bv = make_float2(bias_s[nc], bias_s[nc + 1]);
        int n0 = bn + nc;
        #pragma unroll
        for (int mt = 0; mt < 4; mt++) {
            int m0 = bm + mb + mt * 16 + gr;
            float v00 = tanhf(acc[mt][nt][0] + bv.x);
            float v01 = tanhf(acc[mt][nt][1] + bv.y);
            float v10 = tanhf(acc[mt][nt][2] + bv.x);
            float v11 = tanhf(acc[mt][nt][3] + bv.y);
            *(__half2*)&C[(size_t)m0 * N + n0] = __floats2half2_rn(v00, v01);
            *(__half2*)&C[(size_t)(m0 + 8) * N + n0] = __floats2half2_rn(v10, v11);
        }
    }
}

// ================= decoder v3: 4 targets/warp, ALL loads issued before FMAs =============
__device__ __forceinline__ float dot_u4(uint4 a, uint4 b) {
    float s = 0.f;
    float2 f, g;
    f = __half22float2(*(__half2*)&a.x); g = __half22float2(*(__half2*)&b.x);
    s = fmaf(f.x, g.x, s); s = fmaf(f.y, g.y, s);
    f = __half22float2(*(__half2*)&a.y); g = __half22float2(*(__half2*)&b.y);
    s = fmaf(f.x, g.x, s); s = fmaf(f.y, g.y, s);
    f = __half22float2(*(__half2*)&a.z); g = __half22float2(*(__half2*)&b.z);
    s = fmaf(f.x, g.x, s); s = fmaf(f.y, g.y, s);
    f = __half22float2(*(__half2*)&a.w); g = __half22float2(*(__half2*)&b.w);
    s = fmaf(f.x, g.x, s); s = fmaf(f.y, g.y, s);
    return s;
}

__global__ void __launch_bounds__(256)
k_decode(const int* __restrict__ tuser, const int* __restrict__ titem,
         const float* __restrict__ trating,
         const float* __restrict__ bdec, float* __restrict__ out,
         int nt, int write_loss) {
    int warp = threadIdx.x >> 5, lane = threadIdx.x & 31;
    int base = blockIdx.x * 32 + warp * 4;                 // 8 warps x 4 targets
    bool v[4];
    int tu[4], ti[4];
    #pragma unroll
    for (int p = 0; p < 4; p++) {
        int tt = base + p;
        v[p] = tt < nt;
        tu[p] = v[p] ? tuser[tt] : 0;
        ti[p] = v[p] ? titem[tt] : 0;
    }
    // issue all 16 uint4 loads before any math (MLP = 16/warp)
    uint4 a0[4], a1[4], b0[4], b1[4];
    #pragma unroll
    for (int p = 0; p < 4; p++) {
        const uint4* g = (const uint4*)(g_dec + (size_t)tu[p] * 512);
        const uint4* w = (const uint4*)(g_wdh + (size_t)ti[p] * 512);
        a0[p] = g[lane];
        a1[p] = g[32 + lane];
        b0[p] = w[lane];
        b1[p] = w[32 + lane];
    }
    float s[4];
    #pragma unroll
    for (int p = 0; p < 4; p++)
        s[p] = dot_u4(a0[p], b0[p]) + dot_u4(a1[p], b1[p]);
    #pragma unroll
    for (int o = 16; o; o >>= 1) {
        s[0] += __shfl_xor_sync(0xffffffffu, s[0], o);
        s[1] += __shfl_xor_sync(0xffffffffu, s[1], o);
        s[2] += __shfl_xor_sync(0xffffffffu, s[2], o);
        s[3] += __shfl_xor_sync(0xffffffffu, s[3], o);
    }
    double mine = 0.0;
    if (lane == 0) {
        #pragma unroll
        for (int p = 0; p < 4; p++) {
            if (v[p]) {
                int tt = base + p;
                float pred = s[p] + bdec[ti[p]];
                out[tt] = pred;
                float d = pred - trating[tt];
                mine += (double)d * (double)d;
            }
        }
    }
    __shared__ double part_s[8];
    __shared__ int is_last;
    if (lane == 0) part_s[warp] = mine;
    __syncthreads();
    if (threadIdx.x == 0) {
        double ss = 0.0;
        #pragma unroll
        for (int i = 0; i < 8; i++) ss += part_s[i];
        g_part[blockIdx.x] = ss;
        __threadfence();
        int done = atomicAdd(&g_dcount, 1);
        is_last = (done == (int)gridDim.x - 1);
        if (is_last) g_dcount = 0;                         // self-reset for replay
    }
    __syncthreads();
    if (is_last) {
        int nb = (int)gridDim.x;
        double s2 = 0.0;
        for (int i = threadIdx.x; i < nb; i += 256) s2 += g_part[i];
        __shared__ double red[8];
        #pragma unroll
        for (int o = 16; o; o >>= 1) s2 += __shfl_xor_sync(0xffffffffu, s2, o);
        if (lane == 0) red[warp] = s2;
        __syncthreads();
        if (threadIdx.x == 0) {
            double tot = 0.0;
            #pragma unroll
            for (int i = 0; i < 8; i++) tot += red[i];
            if (write_loss) out[nt] = (float)(tot / (double)nt);
        }
    }
}

// ================= launch (forked graph: sort || prep; wdec-convert || encode+GEMMs) ====
extern "C" void kernel_launch(void* const* d_in, const int* in_sizes, int n_in,
                              void* d_out, int out_size) {
    const int*   user    = (const int*)d_in[0];
    const int*   item    = (const int*)d_in[1];
    const float* rating  = (const float*)d_in[2];
    const int*   tuser   = (const int*)d_in[3];
    const int*   titem   = (const int*)d_in[4];
    const float* trating = (const float*)d_in[5];
    const float* W_enc   = (const float*)d_in[6];
    const float* b_enc   = (const float*)d_in[7];
    const float* W1      = (const float*)d_in[8];
    const float* b1      = (const float*)d_in[9];
    const float* W2      = (const float*)d_in[10];
    const float* b2      = (const float*)d_in[11];
    const float* W_dec   = (const float*)d_in[12];
    const float* b_dec   = (const float*)d_in[13];
    float* out = (float*)d_out;

    int N  = in_sizes[0];
    int NT = in_sizes[3];
    (void)n_in;

    void *cnt_ptr, *x_p, *enc_p, *w1_p, *w2_p, *dec_p;
    cudaGetSymbolAddress(&cnt_ptr, g_cnt);
    cudaGetSymbolAddress(&x_p, g_x);
    cudaGetSymbolAddress(&enc_p, g_enc);
    cudaGetSymbolAddress(&w1_p, g_w1);
    cudaGetSymbolAddress(&w2_p, g_w2);
    cudaGetSymbolAddress(&dec_p, g_dec);

    cudaFuncSetAttribute(k_gemm, cudaFuncAttributeMaxDynamicSharedMemorySize, GEMM_SMEM);

    // side streams + events, created once on the (uncaptured) correctness call
    static cudaStream_t s1 = nullptr, s2 = nullptr;
    static cudaEvent_t evA = nullptr, evB = nullptr, ev1 = nullptr, ev2 = nullptr;
    if (!s1) {
        cudaStreamCreateWithFlags(&s1, cudaStreamNonBlocking);
        cudaStreamCreateWithFlags(&s2, cudaStreamNonBlocking);
        cudaEventCreateWithFlags(&evA, cudaEventDisableTiming);
        cudaEventCreateWithFlags(&evB, cudaEventDisableTiming);
        cudaEventCreateWithFlags(&ev1, cudaEventDisableTiming);
        cudaEventCreateWithFlags(&ev2, cudaEventDisableTiming);
    }

    // main stream: zero counters, then fork sort branch
    cudaMemsetAsync(cnt_ptr, 0, NUM_USERS * sizeof(int), 0);
    cudaEventRecord(evA, 0);

    // ---- branch S (s1): counting sort ----
    cudaStreamWaitEvent(s1, evA, 0);
    k_hist<<<(N + 255) / 256, 256, 0, s1>>>(user, N);
    k_scan<<<1, 1024, 0, s1>>>(N);
    k_scatter<<<(N + 255) / 256, 256, 0, s1>>>(user, item, rating, N);
    cudaEventRecord(ev1, s1);

    // ---- main: transpose W_enc + W1/W2 (parallel with sort) ----
    {
        dim3 g((NUM_ITEMS + 31) / 32, 9);
        k_prep_main<<<g, 256>>>(W_enc, W1, W2);
    }
    cudaEventRecord(evB, 0);

    // ---- branch D (s2): Wdec -> fp16 (parallel with encode + GEMMs) ----
    cudaStreamWaitEvent(s2, evB, 0);
    k_prep_wdec<<<(NUM_ITEMS * H0 / 4 + 255) / 256, 256, 0, s2>>>(W_dec);
    cudaEventRecord(ev2, s2);

    // ---- main: join sort, then encode + GEMMs ----
    cudaStreamWaitEvent(0, ev1, 0);
    k_encode<<<NUM_USERS, 128>>>(b_enc);
    {
        dim3 g1(LAT / 128, NUM_USERS / 128);
        k_gemm<<<g1, 256, GEMM_SMEM>>>((const __half*)x_p, (const __half*)w1_p,
                                       b1, (__half*)enc_p, NUM_USERS, LAT, H0);
        dim3 g2(H0 / 128, NUM_USERS / 128);
        k_gemm<<<g2, 256, GEMM_SMEM>>>((const __half*)enc_p, (const __half*)w2_p,
                                       b2, (__half*)dec_p, NUM_USERS, H0, LAT);
    }

    // ---- main: join Wdec branch, then decode + loss ----
    cudaStreamWaitEvent(0, ev2, 0);
    k_decode<<<(NT + 31) / 32, 256>>>(tuser, titem, trating, b_dec, out, NT,
                                      out_size > NT ? 1 : 0);
}

// round 12
// speedup vs baseline: 1.1360x; 1.0811x over previous
#include <cuda_runtime.h>
#include <cuda_bf16.h>
#include <cuda_fp16.h>
#include <math.h>
#include <stdint.h>

// ---- fixed problem shape ----
#define NUM_ITEMS 50000
#define NUM_USERS 16384
#define H0 512
#define LAT 256
#define NMAX 262144

// ---- scratch ----
static __device__ __half g_WencT[(size_t)NUM_ITEMS * H0];    // fp16 [items, H0]
static __device__ __half g_wdh[(size_t)NUM_ITEMS * H0];      // fp16 Wdec [items, H0]
static __device__ __half g_x[(size_t)NUM_USERS * H0];        // fp16 encoder input
static __device__ __half g_enc[(size_t)NUM_USERS * LAT];     // fp16 latent
static __device__ __half g_w1[(size_t)LAT * H0];             // fp16 W1
static __device__ __half g_w2[(size_t)H0 * LAT];             // fp16 W2
static __device__ __half g_dec[(size_t)NUM_USERS * H0];      // fp16 decoded
static __device__ int    g_cnt[NUM_USERS];
static __device__ int    g_off[NUM_USERS + 1];
static __device__ int    g_cur[NUM_USERS];
static __device__ int    g_pitem[NMAX];
static __device__ float  g_prate[NMAX];
static __device__ double g_part[NMAX / 32];
static __device__ int    g_dcount;

// ================= prep (main): transpose W_enc (fp16, 64h x 32item tiles) + W1/W2 ======
__global__ void k_prep_main(const float* __restrict__ W, const float* __restrict__ W1,
                            const float* __restrict__ W2) {
    int by = blockIdx.y;
    if (by < 8) {
        // transpose W_enc [H0, NUM_ITEMS] -> g_WencT [NUM_ITEMS, H0] (fp16)
        // fp16 stores are full 128B per item row-chunk
        __shared__ float tile[64][33];
        int t = threadIdx.x;
        int txr = t & 31, tr = t >> 5;
        int col0 = blockIdx.x * 32;                        // item base
        int row0 = by * 64;                                // h base
        #pragma unroll
        for (int j = 0; j < 8; j++) {
            int r = tr + j * 8;
            int c = col0 + txr;
            if (c < NUM_ITEMS) tile[r][txr] = W[(size_t)(row0 + r) * NUM_ITEMS + c];
        }
        __syncthreads();
        int txw = t & 31, tw = t >> 5;
        #pragma unroll
        for (int j = 0; j < 4; j++) {
            int il = tw + j * 8;
            int item = col0 + il;
            if (item < NUM_ITEMS) {
                float lo = tile[txw * 2][il];
                float hi = tile[txw * 2 + 1][il];
                ((__half2*)(g_WencT + (size_t)item * H0 + row0))[txw] =
                    __floats2half2_rn(lo, hi);
            }
        }
    } else {
        // W1 / W2 -> fp16
        int i = blockIdx.x * blockDim.x + threadIdx.x;     // float4 units
        const int n1 = LAT * H0 / 4;                       // 32768
        if (i >= 2 * n1) return;
        const float* src; __half* dst; int j;
        if (i < n1) { src = W1; dst = g_w1; j = i; }
        else        { src = W2; dst = g_w2; j = i - n1; }
        float4 v = ((const float4*)src)[j];
        ((__half2*)dst)[j * 2 + 0] = __floats2half2_rn(v.x, v.y);
        ((__half2*)dst)[j * 2 + 1] = __floats2half2_rn(v.z, v.w);
    }
}

// ================= prep (side): Wdec -> fp16 =================
__global__ void k_prep_wdec(const float* __restrict__ Wdec) {
    int idx = blockIdx.x * blockDim.x + threadIdx.x;       // float4 units
    if (idx >= NUM_ITEMS * H0 / 4) return;
    float4 v = ((const float4*)Wdec)[idx];
    ((__half2*)g_wdh)[idx * 2 + 0] = __floats2half2_rn(v.x, v.y);
    ((__half2*)g_wdh)[idx * 2 + 1] = __floats2half2_rn(v.z, v.w);
}

// ================= counting sort =================
__global__ void k_hist(const int* __restrict__ user, int n) {
    int i = blockIdx.x * blockDim.x + threadIdx.x;
    if (i < n) atomicAdd(&g_cnt[user[i]], 1);
}

__global__ void k_scan(int n) {
    int t = threadIdx.x;
    int lane = t & 31, wid = t >> 5;
    int base = t * 16;
    int local[16];
    int s = 0;
    #pragma unroll
    for (int i = 0; i < 16; i++) { local[i] = g_cnt[base + i]; s += local[i]; }
    int v = s;
    #pragma unroll
    for (int o = 1; o < 32; o <<= 1) {
        int u = __shfl_up_sync(0xffffffffu, v, o);
        if (lane >= o) v += u;
    }
    __shared__ int wsum[32];
    if (lane == 31) wsum[wid] = v;
    __syncthreads();
    if (wid == 0) {
        int w = wsum[lane];
        #pragma unroll
        for (int o = 1; o < 32; o <<= 1) {
            int u = __shfl_up_sync(0xffffffffu, w, o);
            if (lane >= o) w += u;
        }
        wsum[lane] = w;
    }
    __syncthreads();
    int run = (wid ? wsum[wid - 1] : 0) + (v - s);
    #pragma unroll
    for (int i = 0; i < 16; i++) {
        g_off[base + i] = run;
        g_cur[base + i] = run;
        run += local[i];
    }
    if (t == 1023) g_off[NUM_USERS] = n;
}

__global__ void k_scatter(const int* __restrict__ user, const int* __restrict__ item,
                          const float* __restrict__ rating, int n) {
    int i = blockIdx.x * blockDim.x + threadIdx.x;
    if (i < n) {
        int p = atomicAdd(&g_cur[user[i]], 1);
        g_pitem[p] = item[i];
        g_prate[p] = rating[i];
    }
}

// ================= encoder aggregation (fp16 gathers, fp32 accum) -> fp16 x =============
__global__ void k_encode(const float* __restrict__ b_enc) {
    int u = blockIdx.x;
    int t = threadIdx.x;                                   // 128; each handles 4 h
    int s = g_off[u], e = g_off[u + 1];
    const uint2* WT = (const uint2*)g_WencT;
    float4 acc0 = make_float4(0.f, 0.f, 0.f, 0.f);
    float4 acc1 = make_float4(0.f, 0.f, 0.f, 0.f);
    __shared__ int   sit[128];
    __shared__ float srt[128];
    for (int j0 = s; j0 < e; j0 += 128) {
        int c = min(128, e - j0);
        if (t < c) { sit[t] = g_pitem[j0 + t]; srt[t] = g_prate[j0 + t]; }
        __syncthreads();
        int q = 0;
        for (; q + 1 < c; q += 2) {
            int i0 = sit[q], i1 = sit[q + 1];
            float r0 = srt[q], r1 = srt[q + 1];
            uint2 w0 = WT[(size_t)i0 * 128 + t];
            uint2 w1 = WT[(size_t)i1 * 128 + t];
            float2 a = __half22float2(*(__half2*)&w0.x);
            float2 b = __half22float2(*(__half2*)&w0.y);
            float2 cc = __half22float2(*(__half2*)&w1.x);
            float2 d = __half22float2(*(__half2*)&w1.y);
            acc0.x = fmaf(r0, a.x, acc0.x); acc1.x = fmaf(r1, cc.x, acc1.x);
            acc0.y = fmaf(r0, a.y, acc0.y); acc1.y = fmaf(r1, cc.y, acc1.y);
            acc0.z = fmaf(r0, b.x, acc0.z); acc1.z = fmaf(r1, d.x, acc1.z);
            acc0.w = fmaf(r0, b.y, acc0.w); acc1.w = fmaf(r1, d.y, acc1.w);
        }
        if (q < c) {
            int i0 = sit[q]; float r0 = srt[q];
            uint2 w0 = WT[(size_t)i0 * 128 + t];
            float2 a = __half22float2(*(__half2*)&w0.x);
            float2 b = __half22float2(*(__half2*)&w0.y);
            acc0.x = fmaf(r0, a.x, acc0.x);
            acc0.y = fmaf(r0, a.y, acc0.y);
            acc0.z = fmaf(r0, b.x, acc0.z);
            acc0.w = fmaf(r0, b.y, acc0.w);
        }
        __syncthreads();
    }
    float4 b = ((const float4*)b_enc)[t];
    float vx = tanhf(acc0.x + acc1.x + b.x);
    float vy = tanhf(acc0.y + acc1.y + b.y);
    float vz = tanhf(acc0.z + acc1.z + b.z);
    float vw = tanhf(acc0.w + acc1.w + b.w);
    size_t o2 = (size_t)u * 256 + t * 2;
    ((__half2*)g_x)[o2 + 0] = __floats2half2_rn(vx, vy);
    ((__half2*)g_x)[o2 + 1] = __floats2half2_rn(vz, vw);
}

// ================= fp16 single-pass tensor-core GEMM =================
#define MMA_F16(c, a0, a1, a2, a3, b0, b1)                                          \
    asm volatile("mma.sync.aligned.m16n8k16.row.col.f32.f16.f16.f32 "               \
                 "{%0,%1,%2,%3},{%4,%5,%6,%7},{%8,%9},{%0,%1,%2,%3};"               \
                 : "+f"(c[0]), "+f"(c[1]), "+f"(c[2]), "+f"(c[3])                   \
                 : "r"(a0), "r"(a1), "r"(a2), "r"(a3), "r"(b0), "r"(b1))

#define SPITCH 136
#define ARRU32 (16 * SPITCH)
#define BUFU32 (2 * ARRU32)
#define GEMM_SMEM ((2 * BUFU32 + 128) * 4)

__global__ void __launch_bounds__(256, 2)
k_gemm(const __half* __restrict__ A, const __half* __restrict__ B,
       const float* __restrict__ bias, __half* __restrict__ C,
       int M, int N, int K) {
    extern __shared__ uint32_t sm[];
    float* bias_s = (float*)(sm + 2 * BUFU32);

    int tid = threadIdx.x;
    int lane = tid & 31;
    int wid = tid >> 5;
    int warp_m = wid & 1;
    int warp_n = wid >> 1;
    int gr = lane >> 2;
    int gc = lane & 3;

    int bm = blockIdx.y * 128;
    int bn = blockIdx.x * 128;

    if (tid < 128) bias_s[tid] = bias[bn + tid];

    float acc[4][4][4];
    #pragma unroll
    for (int i = 0; i < 4; i++)
        #pragma unroll
        for (int j = 0; j < 4; j++)
            #pragma unroll
            for (int q = 0; q < 4; q++) acc[i][j][q] = 0.f;

    const int mb = warp_m * 64;
    const int nb = warp_n * 32;
    const int r    = tid >> 1;
    const int half = tid & 1;
    const int kb2  = half * 8;

    const __half* pA = A + (size_t)(bm + r) * K + half * 16;
    const __half* pB = B + (size_t)(bn + r) * K + half * 16;

    uint4 rA0, rA1, rB0, rB1;

#define LDG_CHUNK(k0)                                                   \
    do {                                                                \
        rA0 = *(const uint4*)(pA + (k0));                               \
        rA1 = *(const uint4*)(pA + (k0) + 8);                           \
        rB0 = *(const uint4*)(pB + (k0));                               \
        rB1 = *(const uint4*)(pB + (k0) + 8);                           \
    } while (0)

#define STS_CHUNK(buf)                                                  \
    do {                                                                \
        uint32_t* bA = sm + (buf) * BUFU32;                             \
        uint32_t* bB = bA + ARRU32;                                     \
        bA[(kb2 + 0) * SPITCH + r] = rA0.x;                             \
        bA[(kb2 + 1) * SPITCH + r] = rA0.y;                             \
        bA[(kb2 + 2) * SPITCH + r] = rA0.z;                             \
        bA[(kb2 + 3) * SPITCH + r] = rA0.w;                             \
        bA[(kb2 + 4) * SPITCH + r] = rA1.x;                             \
        bA[(kb2 + 5) * SPITCH + r] = rA1.y;                             \
        bA[(kb2 + 6) * SPITCH + r] = rA1.z;                             \
        bA[(kb2 + 7) * SPITCH + r] = rA1.w;                             \
        bB[(kb2 + 0) * SPITCH + r] = rB0.x;                             \
        bB[(kb2 + 1) * SPITCH + r] = rB0.y;                             \
        bB[(kb2 + 2) * SPITCH + r] = rB0.z;                             \
        bB[(kb2 + 3) * SPITCH + r] = rB0.w;                             \
        bB[(kb2 + 4) * SPITCH + r] = rB1.x;                             \
        bB[(kb2 + 5) * SPITCH + r] = rB1.y;                             \
        bB[(kb2 + 6) * SPITCH + r] = rB1.z;                             \
        bB[(kb2 + 7) * SPITCH + r] = rB1.w;                             \
    } while (0)

    const int NC = K / 32;
    LDG_CHUNK(0);
    STS_CHUNK(0);
    __syncthreads();

    for (int c = 0; c < NC; c++) {
        if (c + 1 < NC) LDG_CHUNK((c + 1) * 32);

        const uint32_t* bA = sm + (c & 1) * BUFU32;
        const uint32_t* bB = bA + ARRU32;

        #pragma unroll
        for (int ks = 0; ks < 2; ks++) {
            int kb = ks * 8;
            uint32_t Bf[4][2];
            #pragma unroll
            for (int nt = 0; nt < 4; nt++) {
                int n0 = nb + nt * 8 + gr;
                Bf[nt][0] = bB[(kb + gc) * SPITCH + n0];
                Bf[nt][1] = bB[(kb + gc + 4) * SPITCH + n0];
            }
            #pragma unroll
            for (int mt = 0; mt < 4; mt++) {
                int m0 = mb + mt * 16 + gr;
                uint32_t Af[4];
                Af[0] = bA[(kb + gc) * SPITCH + m0];
                Af[1] = bA[(kb + gc) * SPITCH + m0 + 8];
                Af[2] = bA[(kb + gc + 4) * SPITCH + m0];
                Af[3] = bA[(kb + gc + 4) * SPITCH + m0 + 8];
                #pragma unroll
                for (int nt = 0; nt < 4; nt++)
                    MMA_F16(acc[mt][nt], Af[0], Af[1], Af[2], Af[3],
                            Bf[nt][0], Bf[nt][1]);
            }
        }
        if (c + 1 < NC) STS_CHUNK((c + 1) & 1);
        __syncthreads();
    }

    #pragma unroll
    for (int nt = 0; nt < 4; nt++) {
        int nc = nb + nt * 8 + gc * 2;
        float2 bv = make_float2(bias_s[nc], bias_s[nc + 1]);
        int n0 = bn + nc;
        #pragma unroll
        for (int mt = 0; mt < 4; mt++) {
            int m0 = bm + mb + mt * 16 + gr;
            float v00 = tanhf(acc[mt][nt][0] + bv.x);
            float v01 = tanhf(acc[mt][nt][1] + bv.y);
            float v10 = tanhf(acc[mt][nt][2] + bv.x);
            float v11 = tanhf(acc[mt][nt][3] + bv.y);
            *(__half2*)&C[(size_t)m0 * N + n0] = __floats2half2_rn(v00, v01);
            *(__half2*)&C[(size_t)(m0 + 8) * N + n0] = __floats2half2_rn(v10, v11);
        }
    }
}

// ================= decoder (R9 version): 4 targets/warp, 2 waves of 2 interleaved =======
__global__ void k_decode(const int* __restrict__ tuser, const int* __restrict__ titem,
                         const float* __restrict__ trating,
                         const float* __restrict__ bdec, float* __restrict__ out,
                         int nt, int write_loss) {
    int warp = threadIdx.x >> 5, lane = threadIdx.x & 31;
    int base = blockIdx.x * 32 + warp * 4;
    double mine = 0.0;
    #pragma unroll
    for (int p = 0; p < 2; p++) {
        int t0 = base + p * 2;
        int t1 = t0 + 1;
        bool v0 = t0 < nt, v1 = t1 < nt;
        float s0 = 0.f, s1 = 0.f;
        int u0 = 0, i0 = 0, u1 = 0, i1 = 0;
        if (v0) { u0 = tuser[t0]; i0 = titem[t0]; }
        if (v1) { u1 = tuser[t1]; i1 = titem[t1]; }
        const uint4* ga = (const uint4*)(g_dec + (size_t)u0 * 512);
        const uint4* wa = (const uint4*)(g_wdh + (size_t)i0 * 512);
        const uint4* gb = (const uint4*)(g_dec + (size_t)u1 * 512);
        const uint4* wb = (const uint4*)(g_wdh + (size_t)i1 * 512);
        #pragma unroll
        for (int q = 0; q < 2; q++) {
            if (v0) {
                uint4 a = ga[q * 32 + lane];
                uint4 b = wa[q * 32 + lane];
                float2 f, g;
                f = __half22float2(*(__half2*)&a.x); g = __half22float2(*(__half2*)&b.x);
                s0 = fmaf(f.x, g.x, s0); s0 = fmaf(f.y, g.y, s0);
                f = __half22float2(*(__half2*)&a.y); g = __half22float2(*(__half2*)&b.y);
                s0 = fmaf(f.x, g.x, s0); s0 = fmaf(f.y, g.y, s0);
                f = __half22float2(*(__half2*)&a.z); g = __half22float2(*(__half2*)&b.z);
                s0 = fmaf(f.x, g.x, s0); s0 = fmaf(f.y, g.y, s0);
                f = __half22float2(*(__half2*)&a.w); g = __half22float2(*(__half2*)&b.w);
                s0 = fmaf(f.x, g.x, s0); s0 = fmaf(f.y, g.y, s0);
            }
            if (v1) {
                uint4 a = gb[q * 32 + lane];
                uint4 b = wb[q * 32 + lane];
                float2 f, g;
                f = __half22float2(*(__half2*)&a.x); g = __half22float2(*(__half2*)&b.x);
                s1 = fmaf(f.x, g.x, s1); s1 = fmaf(f.y, g.y, s1);
                f = __half22float2(*(__half2*)&a.y); g = __half22float2(*(__half2*)&b.y);
                s1 = fmaf(f.x, g.x, s1); s1 = fmaf(f.y, g.y, s1);
                f = __half22float2(*(__half2*)&a.z); g = __half22float2(*(__half2*)&b.z);
                s1 = fmaf(f.x, g.x, s1); s1 = fmaf(f.y, g.y, s1);
                f = __half22float2(*(__half2*)&a.w); g = __half22float2(*(__half2*)&b.w);
                s1 = fmaf(f.x, g.x, s1); s1 = fmaf(f.y, g.y, s1);
            }
        }
        #pragma unroll
        for (int o = 16; o; o >>= 1) {
            s0 += __shfl_xor_sync(0xffffffffu, s0, o);
            s1 += __shfl_xor_sync(0xffffffffu, s1, o);
        }
        if (lane == 0) {
            if (v0) {
                float pred = s0 + bdec[i0];
                out[t0] = pred;
                float d = pred - trating[t0];
                mine += (double)d * (double)d;
            }
            if (v1) {
                float pred = s1 + bdec[i1];
                out[t1] = pred;
                float d = pred - trating[t1];
                mine += (double)d * (double)d;
            }
        }
    }
    __shared__ double part_s[8];
    __shared__ int is_last;
    if (lane == 0) part_s[warp] = mine;
    __syncthreads();
    if (threadIdx.x == 0) {
        double ss = 0.0;
        #pragma unroll
        for (int i = 0; i < 8; i++) ss += part_s[i];
        g_part[blockIdx.x] = ss;
        __threadfence();
        int done = atomicAdd(&g_dcount, 1);
        is_last = (done == (int)gridDim.x - 1);
        if (is_last) g_dcount = 0;
    }
    __syncthreads();
    if (is_last) {
        int nb = (int)gridDim.x;
        double s = 0.0;
        for (int i = threadIdx.x; i < nb; i += 256) s += g_part[i];
        __shared__ double red[8];
        #pragma unroll
        for (int o = 16; o; o >>= 1) s += __shfl_xor_sync(0xffffffffu, s, o);
        if (lane == 0) red[warp] = s;
        __syncthreads();
        if (threadIdx.x == 0) {
            double tot = 0.0;
            #pragma unroll
            for (int i = 0; i < 8; i++) tot += red[i];
            if (write_loss) out[nt] = (float)(tot / (double)nt);
        }
    }
}

// ================= launch (forked graph: sort || prep; wdec-convert || encode+GEMMs) ====
extern "C" void kernel_launch(void* const* d_in, const int* in_sizes, int n_in,
                              void* d_out, int out_size) {
    const int*   user    = (const int*)d_in[0];
    const int*   item    = (const int*)d_in[1];
    const float* rating  = (const float*)d_in[2];
    const int*   tuser   = (const int*)d_in[3];
    const int*   titem   = (const int*)d_in[4];
    const float* trating = (const float*)d_in[5];
    const float* W_enc   = (const float*)d_in[6];
    const float* b_enc   = (const float*)d_in[7];
    const float* W1      = (const float*)d_in[8];
    const float* b1      = (const float*)d_in[9];
    const float* W2      = (const float*)d_in[10];
    const float* b2      = (const float*)d_in[11];
    const float* W_dec   = (const float*)d_in[12];
    const float* b_dec   = (const float*)d_in[13];
    float* out = (float*)d_out;

    int N  = in_sizes[0];
    int NT = in_sizes[3];
    (void)n_in;

    void *cnt_ptr, *x_p, *enc_p, *w1_p, *w2_p, *dec_p;
    cudaGetSymbolAddress(&cnt_ptr, g_cnt);
    cudaGetSymbolAddress(&x_p, g_x);
    cudaGetSymbolAddress(&enc_p, g_enc);
    cudaGetSymbolAddress(&w1_p, g_w1);
    cudaGetSymbolAddress(&w2_p, g_w2);
    cudaGetSymbolAddress(&dec_p, g_dec);

    cudaFuncSetAttribute(k_gemm, cudaFuncAttributeMaxDynamicSharedMemorySize, GEMM_SMEM);

    // side streams + events, created once on the (uncaptured) correctness call
    static cudaStream_t s1 = nullptr, s2 = nullptr;
    static cudaEvent_t evA = nullptr, evB = nullptr, ev1 = nullptr, ev2 = nullptr;
    if (!s1) {
        cudaStreamCreateWithFlags(&s1, cudaStreamNonBlocking);
        cudaStreamCreateWithFlags(&s2, cudaStreamNonBlocking);
        cudaEventCreateWithFlags(&evA, cudaEventDisableTiming);
        cudaEventCreateWithFlags(&evB, cudaEventDisableTiming);
        cudaEventCreateWithFlags(&ev1, cudaEventDisableTiming);
        cudaEventCreateWithFlags(&ev2, cudaEventDisableTiming);
    }

    // main stream: zero counters, then fork sort branch
    cudaMemsetAsync(cnt_ptr, 0, NUM_USERS * sizeof(int), 0);
    cudaEventRecord(evA, 0);

    // ---- branch S (s1): counting sort ----
    cudaStreamWaitEvent(s1, evA, 0);
    k_hist<<<(N + 255) / 256, 256, 0, s1>>>(user, N);
    k_scan<<<1, 1024, 0, s1>>>(N);
    k_scatter<<<(N + 255) / 256, 256, 0, s1>>>(user, item, rating, N);
    cudaEventRecord(ev1, s1);

    // ---- main: transpose W_enc + W1/W2 (parallel with sort) ----
    {
        dim3 g((NUM_ITEMS + 31) / 32, 9);
        k_prep_main<<<g, 256>>>(W_enc, W1, W2);
    }
    cudaEventRecord(evB, 0);

    // ---- branch D (s2): Wdec -> fp16 (parallel with encode + GEMMs) ----
    cudaStreamWaitEvent(s2, evB, 0);
    k_prep_wdec<<<(NUM_ITEMS * H0 / 4 + 255) / 256, 256, 0, s2>>>(W_dec);
    cudaEventRecord(ev2, s2);

    // ---- main: join sort, then encode + GEMMs ----
    cudaStreamWaitEvent(0, ev1, 0);
    k_encode<<<NUM_USERS, 128>>>(b_enc);
    {
        dim3 g1(LAT / 128, NUM_USERS / 128);
        k_gemm<<<g1, 256, GEMM_SMEM>>>((const __half*)x_p, (const __half*)w1_p,
                                       b1, (__half*)enc_p, NUM_USERS, LAT, H0);
        dim3 g2(H0 / 128, NUM_USERS / 128);
        k_gemm<<<g2, 256, GEMM_SMEM>>>((const __half*)enc_p, (const __half*)w2_p,
                                       b2, (__half*)dec_p, NUM_USERS, H0, LAT);
    }

    // ---- main: join Wdec branch, then decode + loss ----
    cudaStreamWaitEvent(0, ev2, 0);
    k_decode<<<(NT + 31) / 32, 256>>>(tuser, titem, trating, b_dec, out, NT,
                                      out_size > NT ? 1 : 0);
}